// round 14
// baseline (speedup 1.0000x reference)
#include <cuda_runtime.h>
#include <cuda_bf16.h>
#include <math.h>

// Problem constants (fixed by the reference)
#define BB   4
#define HH   56
#define WW   56
#define Csz  192
#define Gsz  12
#define CG   16
#define Kpts 8
#define HID  768
#define HP   58
#define WP   58
#define NTOK (BB*HH*WW)          // 12544
#define PADSP (HP*WP)            // 3364
#define NOM  288                  // off(192) + mask(96) concatenated

// ---------------- scratch (device globals; no allocation) ----------------
__device__ float g_xln[NTOK*Csz];
__device__ float g_pad[BB*PADSP*Csz];      // padded value (in_proj output)
__device__ float g_x1 [NTOK*Csz];          // dwconv+LN+GELU (tf32-rounded)
__device__ float g_off[NTOK*Csz];          // G*K*2 = 192
__device__ float g_msk[NTOK*Gsz*Kpts];     // 96 logits
__device__ float g_dcn[NTOK*Csz];          // sampling output (tf32-rounded)
__device__ float g_d  [NTOK*Csz];          // out_proj output (K-half 0)
__device__ float g_db [NTOK*Csz];          // out_proj output (K-half 1)
__device__ float g_x2 [NTOK*Csz];          // x + LN(d)
__device__ float g_t  [NTOK*Csz];          // LN(x2, norm2) (tf32-rounded)
__device__ float g_h1 [NTOK*HID];          // (tf32-rounded)
__device__ float g_h2 [NTOK*Csz];          // fc2 output (K-half 0)
__device__ float g_h2b[NTOK*Csz];          // fc2 output (K-half 1)
__device__ float g_zero[Csz];              // zero bias (never written)
// tf32-rounded weight copies
__device__ float g_w1 [Csz*Csz];           // in_proj
__device__ float g_wom[Csz*NOM];           // off | mask concat
__device__ float g_bom[NOM];               // off_b | mask_b concat
__device__ float g_w2 [Csz*Csz];           // out_proj
__device__ float g_w3 [Csz*HID];           // fc1
__device__ float g_w4 [HID*Csz];           // fc2

// ---------------- helpers ----------------
__device__ __forceinline__ float gelu_exact(float x) {
    return 0.5f * x * (1.0f + erff(x * 0.70710678118654752f));
}

__device__ __forceinline__ float round_tf32(float x) {
    unsigned r;
    asm("cvt.rna.tf32.f32 %0, %1;" : "=r"(r) : "f"(x));
    return __uint_as_float(r);
}

__device__ __forceinline__ unsigned smem_u32(const void* p) {
    return (unsigned)__cvta_generic_to_shared(p);
}

__device__ __forceinline__ void cp_async16(unsigned dst, const void* src, int src_bytes) {
    asm volatile("cp.async.cg.shared.global [%0], [%1], 16, %2;"
                 :: "r"(dst), "l"(src), "r"(src_bytes));
}

// ---------------- setup work sizes ----------------
#define W1_SZ (Csz*Csz)
#define WOM_SZ (Csz*NOM)
#define W3_SZ (Csz*HID)
#define PREP_TOTAL (W1_SZ + WOM_SZ + W1_SZ + W3_SZ + W3_SZ + NOM)
#define BORDER_TOTAL (BB*228*Csz)
#define SETUP_TOTAL (PREP_TOTAL + BORDER_TOTAL)
#define SETUP_BLOCKS 684

__device__ __forceinline__ void setup_work(int i,
        const float* ipw, const float* offw, const float* maskw,
        const float* opw, const float* f1w, const float* f2w,
        const float* offb, const float* maskb) {
    int j = i;
    if (j < BORDER_TOTAL) {
        const int per_img = 228 * Csz;
        int b = j / per_img;
        int r = j % per_img;
        int cell = r / Csz, c = r % Csz;
        int h, w;
        if      (cell < 58)  { h = 0;              w = cell; }
        else if (cell < 116) { h = HP-1;           w = cell - 58; }
        else if (cell < 172) { h = cell - 116 + 1; w = 0; }
        else                 { h = cell - 172 + 1; w = WP-1; }
        g_pad[((size_t)b*PADSP + (size_t)h*WP + w)*Csz + c] = 0.f;
        return;
    }
    j -= BORDER_TOTAL;
    if (j < W1_SZ) { g_w1[j] = round_tf32(ipw[j]); return; }
    j -= W1_SZ;
    if (j < WOM_SZ) {
        int row = j / NOM, col = j % NOM;
        float v = (col < Csz) ? offw[row*(Gsz*Kpts*2) + col] : maskw[row*(Gsz*Kpts) + col - Csz];
        g_wom[j] = round_tf32(v);
        return;
    }
    j -= WOM_SZ;
    if (j < W1_SZ) { g_w2[j] = round_tf32(opw[j]); return; }
    j -= W1_SZ;
    if (j < W3_SZ) { g_w3[j] = round_tf32(f1w[j]); return; }
    j -= W3_SZ;
    if (j < W3_SZ) { g_w4[j] = round_tf32(f2w[j]); return; }
    j -= W3_SZ;
    g_bom[j] = (j < Csz) ? offb[j] : maskb[j - Csz];
}

// ---------------- fat kernel A: LN(x, norm1) -> xln (rounded)  +  setup ----
__global__ void lnsetup_kernel(const float* __restrict__ x,
                               const float* __restrict__ w, const float* __restrict__ b,
                               const float* __restrict__ ipw,
                               const float* __restrict__ offw, const float* __restrict__ maskw,
                               const float* __restrict__ opw,
                               const float* __restrict__ f1w, const float* __restrict__ f2w,
                               const float* __restrict__ offb, const float* __restrict__ maskb) {
    if (blockIdx.x >= NTOK) {
        int base = (blockIdx.x - NTOK) * blockDim.x + threadIdx.x;
        for (int i = base; i < SETUP_TOTAL; i += SETUP_BLOCKS * blockDim.x)
            setup_work(i, ipw, offw, maskw, opw, f1w, f2w, offb, maskb);
        return;
    }
    int n = blockIdx.x;
    int c = threadIdx.x;
    float v = x[n*Csz + c];
    float s = v, s2 = v*v;
    #pragma unroll
    for (int o = 16; o; o >>= 1) {
        s  += __shfl_xor_sync(0xffffffffu, s,  o);
        s2 += __shfl_xor_sync(0xffffffffu, s2, o);
    }
    __shared__ float red[12];
    int wid = c >> 5, lane = c & 31;
    if (lane == 0) { red[wid] = s; red[6+wid] = s2; }
    __syncthreads();
    if (c == 0) {
        float S = 0.f, S2 = 0.f;
        #pragma unroll
        for (int i = 0; i < 6; i++) { S += red[i]; S2 += red[6+i]; }
        red[0] = S; red[6] = S2;
    }
    __syncthreads();
    float mu  = red[0] * (1.0f/Csz);
    float var = red[6] * (1.0f/Csz) - mu*mu;
    g_xln[n*Csz + c] = round_tf32((v - mu) * rsqrtf(var + 1e-5f) * w[c] + b[c]);
}

// ---------------- generic LN kernel: out = LN(in [+ in2])*w+b (+ res) ----
__global__ void ln_kernel(const float* __restrict__ in, const float* __restrict__ in2,
                          const float* __restrict__ res,
                          const float* __restrict__ w, const float* __restrict__ b,
                          float* __restrict__ out, float eps, int rnd) {
    int n = blockIdx.x;
    int c = threadIdx.x;
    float v = in[n*Csz + c];
    if (in2) v += in2[n*Csz + c];
    float s = v, s2 = v*v;
    #pragma unroll
    for (int o = 16; o; o >>= 1) {
        s  += __shfl_xor_sync(0xffffffffu, s,  o);
        s2 += __shfl_xor_sync(0xffffffffu, s2, o);
    }
    __shared__ float red[12];
    int wid = c >> 5, lane = c & 31;
    if (lane == 0) { red[wid] = s; red[6+wid] = s2; }
    __syncthreads();
    if (c == 0) {
        float S = 0.f, S2 = 0.f;
        #pragma unroll
        for (int i = 0; i < 6; i++) { S += red[i]; S2 += red[6+i]; }
        red[0] = S; red[6] = S2;
    }
    __syncthreads();
    float mu  = red[0] * (1.0f/Csz);
    float var = red[6] * (1.0f/Csz) - mu*mu;
    float o = (v - mu) * rsqrtf(var + eps) * w[c] + b[c];
    if (res) o += res[n*Csz + c];
    if (rnd) o = round_tf32(o);
    out[n*Csz + c] = o;
}

// ---------------- fused: x2 = x + LN(d+d2, rpn1); t = round(LN(x2, norm2)) ----
__global__ void ln_fuse2_kernel(const float* __restrict__ d_in, const float* __restrict__ d2_in,
                                const float* __restrict__ x_in,
                                const float* __restrict__ w1, const float* __restrict__ b1,
                                const float* __restrict__ w2, const float* __restrict__ b2,
                                float* __restrict__ x2_out, float* __restrict__ t_out) {
    int n = blockIdx.x;
    int c = threadIdx.x;
    __shared__ float red[12];
    int wid = c >> 5, lane = c & 31;

    float v = d_in[n*Csz + c] + d2_in[n*Csz + c];
    float s = v, s2 = v*v;
    #pragma unroll
    for (int o = 16; o; o >>= 1) {
        s  += __shfl_xor_sync(0xffffffffu, s,  o);
        s2 += __shfl_xor_sync(0xffffffffu, s2, o);
    }
    if (lane == 0) { red[wid] = s; red[6+wid] = s2; }
    __syncthreads();
    if (c == 0) {
        float S = 0.f, S2 = 0.f;
        #pragma unroll
        for (int i = 0; i < 6; i++) { S += red[i]; S2 += red[6+i]; }
        red[0] = S; red[6] = S2;
    }
    __syncthreads();
    float mu  = red[0] * (1.0f/Csz);
    float var = red[6] * (1.0f/Csz) - mu*mu;
    float x2 = x_in[n*Csz + c] + (v - mu) * rsqrtf(var + 1e-5f) * w1[c] + b1[c];
    x2_out[n*Csz + c] = x2;
    __syncthreads();   // red[] reuse

    s = x2; s2 = x2*x2;
    #pragma unroll
    for (int o = 16; o; o >>= 1) {
        s  += __shfl_xor_sync(0xffffffffu, s,  o);
        s2 += __shfl_xor_sync(0xffffffffu, s2, o);
    }
    if (lane == 0) { red[wid] = s; red[6+wid] = s2; }
    __syncthreads();
    if (c == 0) {
        float S = 0.f, S2 = 0.f;
        #pragma unroll
        for (int i = 0; i < 6; i++) { S += red[i]; S2 += red[6+i]; }
        red[0] = S; red[6] = S2;
    }
    __syncthreads();
    mu  = red[0] * (1.0f/Csz);
    var = red[6] * (1.0f/Csz) - mu*mu;
    t_out[n*Csz + c] = round_tf32((x2 - mu) * rsqrtf(var + 1e-5f) * w2[c] + b2[c]);
}

// ---------------- GEMM tile body (128x64, 2-stage cp.async, tf32) ----------
// lda = A row stride (elements); K = reduction length for this call.
#define AS_STRIDE 20
#define BS_STRIDE 72
struct GemmSmem {
    float As[2][128*AS_STRIDE];
    float Bs[2][16*BS_STRIDE];
};

__device__ __forceinline__ void gemm_tile_body(
        GemmSmem* sm, const float* __restrict__ A, const float* __restrict__ W,
        const float* __restrict__ bias, float* __restrict__ C,
        int M, int N, int K, int lda, int row0, int col0, int act, int out_mode, int rnd) {
    int tid = threadIdx.x;
    int lane = tid & 31, warp = tid >> 5;
    int gid = lane >> 2, tig = lane & 3;
    int wr = (warp >> 1) * 32;
    int wc = (warp & 1) * 32;

    int a_row = tid >> 1;
    int a_k   = (tid & 1) * 8;
    int b_row = tid >> 4;
    int b_n   = (tid & 15) * 4;

    const float* Abase = A + (size_t)(row0 + a_row)*lda + a_k;
    const float* Wbase = W + (size_t)b_row*N + col0 + b_n;
    int b_valid = (col0 + b_n + 4 <= N) ? 16 : 0;

    unsigned as_dst0 = smem_u32(&sm->As[0][a_row*AS_STRIDE + a_k]);
    unsigned as_dst1 = smem_u32(&sm->As[1][a_row*AS_STRIDE + a_k]);
    unsigned bs_dst0 = smem_u32(&sm->Bs[0][b_row*BS_STRIDE + b_n]);
    unsigned bs_dst1 = smem_u32(&sm->Bs[1][b_row*BS_STRIDE + b_n]);

    float acc[2][4][4];
    #pragma unroll
    for (int mi = 0; mi < 2; mi++)
        #pragma unroll
        for (int ni = 0; ni < 4; ni++)
            #pragma unroll
            for (int r = 0; r < 4; r++) acc[mi][ni][r] = 0.f;

    int stages = K / 16;

    cp_async16(as_dst0,      Abase,     16);
    cp_async16(as_dst0 + 16, Abase + 4, 16);
    cp_async16(bs_dst0, Wbase, b_valid);
    asm volatile("cp.async.commit_group;");

    for (int it = 0; it < stages; it++) {
        asm volatile("cp.async.wait_group 0;");
        __syncthreads();

        if (it + 1 < stages) {
            int k0n = (it + 1) * 16;
            const float* An = Abase + k0n;
            const float* Wn = Wbase + (size_t)k0n * N;
            unsigned ad = ((it + 1) & 1) ? as_dst1 : as_dst0;
            unsigned bd = ((it + 1) & 1) ? bs_dst1 : bs_dst0;
            cp_async16(ad,      An,     16);
            cp_async16(ad + 16, An + 4, 16);
            cp_async16(bd, Wn, b_valid);
            asm volatile("cp.async.commit_group;");
        }

        const unsigned* as = (const unsigned*)sm->As[it & 1];
        const unsigned* bs = (const unsigned*)sm->Bs[it & 1];
        #pragma unroll
        for (int ks = 0; ks < 2; ks++) {
            int kb = ks * 8;
            unsigned af[2][4], bf[4][2];
            #pragma unroll
            for (int mi = 0; mi < 2; mi++) {
                int mrow = wr + mi*16 + gid;
                af[mi][0] = as[ mrow   *AS_STRIDE + kb + tig    ];
                af[mi][1] = as[(mrow+8)*AS_STRIDE + kb + tig    ];
                af[mi][2] = as[ mrow   *AS_STRIDE + kb + tig + 4];
                af[mi][3] = as[(mrow+8)*AS_STRIDE + kb + tig + 4];
            }
            #pragma unroll
            for (int ni = 0; ni < 4; ni++) {
                int ncol = wc + ni*8 + gid;
                bf[ni][0] = bs[(kb + tig    )*BS_STRIDE + ncol];
                bf[ni][1] = bs[(kb + tig + 4)*BS_STRIDE + ncol];
            }
            #pragma unroll
            for (int mi = 0; mi < 2; mi++)
                #pragma unroll
                for (int ni = 0; ni < 4; ni++) {
                    asm volatile(
                        "mma.sync.aligned.m16n8k8.row.col.f32.tf32.tf32.f32 "
                        "{%0,%1,%2,%3}, {%4,%5,%6,%7}, {%8,%9}, {%0,%1,%2,%3};"
                        : "+f"(acc[mi][ni][0]), "+f"(acc[mi][ni][1]),
                          "+f"(acc[mi][ni][2]), "+f"(acc[mi][ni][3])
                        : "r"(af[mi][0]), "r"(af[mi][1]), "r"(af[mi][2]), "r"(af[mi][3]),
                          "r"(bf[ni][0]), "r"(bf[ni][1]));
                }
        }
        __syncthreads();
    }

    #pragma unroll
    for (int mi = 0; mi < 2; mi++) {
        #pragma unroll
        for (int ni = 0; ni < 4; ni++) {
            int r0 = row0 + wr + mi*16 + gid;
            int c0 = col0 + wc + ni*8 + 2*tig;
            #pragma unroll
            for (int rr = 0; rr < 2; rr++) {
                int row = r0 + rr*8;
                #pragma unroll
                for (int cc = 0; cc < 2; cc++) {
                    int col = c0 + cc;
                    if (col >= N) continue;
                    float v = acc[mi][ni][rr*2 + cc] + bias[col];
                    if (act == 1) v = gelu_exact(v);
                    if (rnd) v = round_tf32(v);
                    if (out_mode == 1) {
                        int bimg = row / (HH*WW);
                        int hw = row % (HH*WW);
                        int h = hw / WW, w = hw % WW;
                        g_pad[((size_t)bimg*PADSP + (size_t)(h+1)*WP + (w+1))*Csz + col] = v;
                    } else if (out_mode == 2) {
                        if (col < Csz) g_off[(size_t)row*Csz + col] = v;
                        else           g_msk[(size_t)row*(Gsz*Kpts) + col - Csz] = v;
                    } else {
                        C[(size_t)row*N + col] = v;
                    }
                }
            }
        }
    }
}

// ---------------- generic GEMM kernel ----------------
__global__ __launch_bounds__(256) void gemm_tf32_kernel(
        const float* __restrict__ A, const float* __restrict__ W,
        const float* __restrict__ bias, float* __restrict__ C,
        int M, int N, int K, int act, int out_mode, int rnd) {
    __shared__ GemmSmem sm;
    gemm_tile_body(&sm, A, W, bias, C, M, N, K, K, blockIdx.y*128, blockIdx.x*64,
                   act, out_mode, rnd);
}

// ---------------- split-K GEMM kernel (gridDim.z = 2 halves, one launch) ----
// z=0: C  = A[:, :Khalf] @ W[:Khalf] + bias
// z=1: C2 = A[:, Khalf:] @ W[Khalf:] + 0     (downstream kernel sums)
__global__ __launch_bounds__(256) void gemm_splitk_kernel(
        const float* __restrict__ A, const float* __restrict__ W,
        const float* __restrict__ bias, const float* __restrict__ bias2,
        float* __restrict__ C, float* __restrict__ C2,
        int M, int N, int Khalf, int lda) {
    __shared__ GemmSmem sm;
    int z = blockIdx.z;
    gemm_tile_body(&sm, A + (size_t)z*Khalf, W + (size_t)z*Khalf*N,
                   z ? bias2 : bias, z ? C2 : C,
                   M, N, Khalf, lda, blockIdx.y*128, blockIdx.x*64, 0, 0, 0);
}

// ---------------- fat kernel B: in_proj GEMM + depthwise conv ----------
#define GEMM_BLOCKS (3*(NTOK/128))        // 294
#define DW_BLOCKS   (BB*(HH/4)*WW)        // 3136
__global__ __launch_bounds__(256) void inproj_dw_kernel(
        const float* __restrict__ in_proj_b,
        const float* __restrict__ dww, const float* __restrict__ dwb,
        const float* __restrict__ lnw, const float* __restrict__ lnb) {
    __shared__ GemmSmem sm;   // dw path reuses the first bytes for its reduction
    if (blockIdx.x < GEMM_BLOCKS) {
        int gb = blockIdx.x;
        int col0 = (gb % 3) * 64;
        int row0 = (gb / 3) * 128;
        gemm_tile_body(&sm, g_xln, g_w1, in_proj_b, nullptr, NTOK, Csz, Csz, Csz,
                       row0, col0, 0, 1, 0);
        return;
    }
    // ---- dw path: 4 tokens (h0..h0+3, w) ----
    float* redS = (float*)&sm;            // 4*6 sums + 4*6 sqsums = 48 floats
    int blk = blockIdx.x - GEMM_BLOCKS;
    int bimg = blk / ((HH/4)*WW);
    int r = blk % ((HH/4)*WW);
    int h0 = (r / WW) * 4;
    int w = r % WW;
    int c = threadIdx.x;                  // only c < 192 active
    int wid = c >> 5, lane = c & 31;

    float accj[4] = {0.f, 0.f, 0.f, 0.f};
    float s[4], s2[4];
    if (c < Csz) {
        float wt[9];
        #pragma unroll
        for (int i = 0; i < 9; i++) wt[i] = dww[i*Csz + c];
        float vals[6][3];
        #pragma unroll
        for (int rr = 0; rr < 6; rr++) {
            int hh = h0 - 1 + rr;
            #pragma unroll
            for (int cc = 0; cc < 3; cc++) {
                int ww = w - 1 + cc;
                float v = 0.f;
                if (hh >= 0 && hh < HH && ww >= 0 && ww < WW)
                    v = g_xln[((bimg*HH + hh)*WW + ww)*Csz + c];
                vals[rr][cc] = v;
            }
        }
        float bc = dwb[c];
        #pragma unroll
        for (int j = 0; j < 4; j++) {
            float a = 0.f;
            #pragma unroll
            for (int ky = 0; ky < 3; ky++)
                #pragma unroll
                for (int kx = 0; kx < 3; kx++)
                    a += vals[j + ky][kx] * wt[ky*3 + kx];
            accj[j] = a + bc;
        }
        #pragma unroll
        for (int j = 0; j < 4; j++) { s[j] = accj[j]; s2[j] = accj[j]*accj[j]; }
        #pragma unroll
        for (int o = 16; o; o >>= 1) {
            #pragma unroll
            for (int j = 0; j < 4; j++) {
                s[j]  += __shfl_xor_sync(0xffffffffu, s[j],  o);
                s2[j] += __shfl_xor_sync(0xffffffffu, s2[j], o);
            }
        }
        if (lane == 0) {
            #pragma unroll
            for (int j = 0; j < 4; j++) {
                redS[j*6 + wid]      = s[j];
                redS[24 + j*6 + wid] = s2[j];
            }
        }
    }
    __syncthreads();
    if (c < Csz) {
        float lw = lnw[c], lb = lnb[c];
        #pragma unroll
        for (int j = 0; j < 4; j++) {
            float S = 0.f, S2 = 0.f;
            #pragma unroll
            for (int i = 0; i < 6; i++) { S += redS[j*6 + i]; S2 += redS[24 + j*6 + i]; }
            float mu  = S * (1.0f/Csz);
            float var = S2 * (1.0f/Csz) - mu*mu;
            float y = (accj[j] - mu) * rsqrtf(var + 1e-6f) * lw + lb;
            int n = (bimg*HH + h0 + j)*WW + w;
            g_x1[n*Csz + c] = round_tf32(gelu_exact(y));
        }
    }
}

// ---------------- DCNv3 sampling: 8 channels/thread, 8 tokens/block ----------
// 192 threads = 8 tokens x 24 threads; within a token: group g = tt/2,
// lane-in-group l = tt%2, channels g*16 + 8l .. 8l+7 (2x float4).
__global__ __launch_bounds__(192) void dcn_sample_kernel(
        const float* __restrict__ cfs_w, const float* __restrict__ cfs_b,
        float* __restrict__ out) {
    int t = threadIdx.x;
    int tok = t / 24;
    int tt = t % 24;
    int n = blockIdx.x * 8 + tok;
    int g = tt >> 1, l = tt & 1;
    int bimg = n / (HH*WW);
    int hw = n % (HH*WW);
    int h = hw / WW, w = hw % WW;

    __shared__ float4 x1s[8][48];
    x1s[tok][tt*2]     = *(const float4*)&g_x1[n*Csz + tt*8];
    x1s[tok][tt*2 + 1] = *(const float4*)&g_x1[n*Csz + tt*8 + 4];
    __syncthreads();

    // center feature scale: sigmoid( x1 . cfs_w[g,:] + cfs_b[g] ), 2 lanes
    const float4* cwv = (const float4*)(cfs_w + g*Csz);
    float p = 0.f;
    #pragma unroll
    for (int c = l; c < Csz/4; c += 2) {
        float4 a = x1s[tok][c], b = cwv[c];
        p += a.x*b.x + a.y*b.y + a.z*b.z + a.w*b.w;
    }
    p += __shfl_xor_sync(0xffffffffu, p, 1, 2);
    float cfsv = 1.0f / (1.0f + expf(-(p + cfs_b[g])));

    // softmax over K=8 mask logits (redundant per 2 lanes of a group; cheap)
    float m[Kpts];
    float mx = -1e30f;
    #pragma unroll
    for (int k = 0; k < Kpts; k++) {
        m[k] = g_msk[n*(Gsz*Kpts) + g*Kpts + k];
        mx = fmaxf(mx, m[k]);
    }
    float msum = 0.f;
    #pragma unroll
    for (int k = 0; k < Kpts; k++) { m[k] = expf(m[k] - mx); msum += m[k]; }
    float minv = 1.0f / msum;

    const float gx[Kpts] = {-1,-1,-1, 0, 0, 1, 1, 1};
    const float gy[Kpts] = {-1, 0, 1,-1, 1,-1, 0, 1};
    const float* vb = g_pad + (size_t)bimg*PADSP*Csz;
    int ch = g*CG + 8*l;

    float acc[8] = {0.f,0.f,0.f,0.f,0.f,0.f,0.f,0.f};
    #pragma unroll
    for (int k = 0; k < Kpts; k++) {
        float ox = g_off[n*Csz + (g*Kpts + k)*2 + 0];
        float oy = g_off[n*Csz + (g*Kpts + k)*2 + 1];
        float px = (float)(w + 1) + gx[k] + ox;
        float py = (float)(h + 1) + gy[k] + oy;
        float x0 = floorf(px), y0 = floorf(py);
        float wx = px - x0, wy = py - y0;
        int ix0 = (int)x0, iy0 = (int)y0;

        float w00 = (1.f-wy)*(1.f-wx), w01 = (1.f-wy)*wx;
        float w10 = wy*(1.f-wx),       w11 = wy*wx;

        float sv[8] = {0.f,0.f,0.f,0.f,0.f,0.f,0.f,0.f};
        #pragma unroll
        for (int cy = 0; cy < 2; cy++) {
            #pragma unroll
            for (int cx = 0; cx < 2; cx++) {
                int iy = iy0 + cy, ix = ix0 + cx;
                if (iy >= 0 && iy < HP && ix >= 0 && ix < WP) {
                    const float4* pp = (const float4*)&vb[((size_t)iy*WP + ix)*Csz + ch];
                    float4 a = pp[0], bq = pp[1];
                    float wcc = (cy ? (cx ? w11 : w10) : (cx ? w01 : w00));
                    sv[0] += a.x*wcc;  sv[1] += a.y*wcc;
                    sv[2] += a.z*wcc;  sv[3] += a.w*wcc;
                    sv[4] += bq.x*wcc; sv[5] += bq.y*wcc;
                    sv[6] += bq.z*wcc; sv[7] += bq.w*wcc;
                }
            }
        }
        float mk = m[k]*minv;
        #pragma unroll
        for (int i = 0; i < 8; i++) acc[i] += mk * sv[i];
    }

    const float4* xp = (const float4*)&vb[((size_t)(h+1)*WP + (w+1))*Csz + ch];
    float4 xa = xp[0], xb = xp[1];
    float4 o0, o1;
    o0.x = round_tf32(acc[0]*(1.0f - cfsv) + xa.x*cfsv);
    o0.y = round_tf32(acc[1]*(1.0f - cfsv) + xa.y*cfsv);
    o0.z = round_tf32(acc[2]*(1.0f - cfsv) + xa.z*cfsv);
    o0.w = round_tf32(acc[3]*(1.0f - cfsv) + xa.w*cfsv);
    o1.x = round_tf32(acc[4]*(1.0f - cfsv) + xb.x*cfsv);
    o1.y = round_tf32(acc[5]*(1.0f - cfsv) + xb.y*cfsv);
    o1.z = round_tf32(acc[6]*(1.0f - cfsv) + xb.z*cfsv);
    o1.w = round_tf32(acc[7]*(1.0f - cfsv) + xb.w*cfsv);
    *(float4*)&out[n*Csz + ch]     = o0;
    *(float4*)&out[n*Csz + ch + 4] = o1;
}

// ---------------- launch ----------------
extern "C" void kernel_launch(void* const* d_in, const int* in_sizes, int n_in,
                              void* d_out, int out_size) {
    const float* x        = (const float*)d_in[0];
    const float* norm1_w  = (const float*)d_in[1];
    const float* norm1_b  = (const float*)d_in[2];
    const float* norm2_w  = (const float*)d_in[3];
    const float* norm2_b  = (const float*)d_in[4];
    const float* rpn1_w   = (const float*)d_in[5];
    const float* rpn1_b   = (const float*)d_in[6];
    const float* rpn2_w   = (const float*)d_in[7];
    const float* rpn2_b   = (const float*)d_in[8];
    const float* in_proj_w= (const float*)d_in[9];
    const float* in_proj_b= (const float*)d_in[10];
    const float* dw_w     = (const float*)d_in[11];
    const float* dw_b     = (const float*)d_in[12];
    const float* dw_ln_w  = (const float*)d_in[13];
    const float* dw_ln_b  = (const float*)d_in[14];
    const float* off_w    = (const float*)d_in[15];
    const float* off_b    = (const float*)d_in[16];
    const float* mask_w   = (const float*)d_in[17];
    const float* mask_b   = (const float*)d_in[18];
    const float* cfs_w    = (const float*)d_in[19];
    const float* cfs_b    = (const float*)d_in[20];
    const float* out_proj_w = (const float*)d_in[21];
    const float* out_proj_b = (const float*)d_in[22];
    const float* fc1_w    = (const float*)d_in[23];
    const float* fc1_b    = (const float*)d_in[24];
    const float* fc2_w    = (const float*)d_in[25];
    const float* fc2_b    = (const float*)d_in[26];
    float* outp = (float*)d_out;

    float *p_dcn, *p_d, *p_db, *p_x2, *p_t, *p_h1, *p_h2, *p_h2b, *p_zero;
    float *p_x1, *p_wom, *p_bom, *p_w2, *p_w3, *p_w4;
    cudaGetSymbolAddress((void**)&p_x1,  g_x1);
    cudaGetSymbolAddress((void**)&p_dcn, g_dcn);
    cudaGetSymbolAddress((void**)&p_d,   g_d);
    cudaGetSymbolAddress((void**)&p_db,  g_db);
    cudaGetSymbolAddress((void**)&p_x2,  g_x2);
    cudaGetSymbolAddress((void**)&p_t,   g_t);
    cudaGetSymbolAddress((void**)&p_h1,  g_h1);
    cudaGetSymbolAddress((void**)&p_h2,  g_h2);
    cudaGetSymbolAddress((void**)&p_h2b, g_h2b);
    cudaGetSymbolAddress((void**)&p_zero,g_zero);
    cudaGetSymbolAddress((void**)&p_wom, g_wom);
    cudaGetSymbolAddress((void**)&p_bom, g_bom);
    cudaGetSymbolAddress((void**)&p_w2,  g_w2);
    cudaGetSymbolAddress((void**)&p_w3,  g_w3);
    cudaGetSymbolAddress((void**)&p_w4,  g_w4);

    dim3 thr256(256);
    const int MT = NTOK/128;   // 98 M-tiles

    // 1. LN(x, norm1) + setup (pad border, rounded weights) — one fat launch
    lnsetup_kernel<<<NTOK + SETUP_BLOCKS, Csz>>>(x, norm1_w, norm1_b,
        in_proj_w, off_w, mask_w, out_proj_w, fc1_w, fc2_w, off_b, mask_b);

    // 2. in_proj GEMM (-> padded value buffer)  +  dwconv/LN/GELU — one fat launch
    inproj_dw_kernel<<<GEMM_BLOCKS + DW_BLOCKS, thr256>>>(in_proj_b, dw_w, dw_b,
        dw_ln_w, dw_ln_b);

    // 3. off|mask = x1 @ [off_w|mask_w] + bias   (merged, N=288)
    gemm_tf32_kernel<<<dim3(5, MT), thr256>>>(p_x1, p_wom, p_bom, nullptr, NTOK, NOM, Csz, 0, 2, 0);

    // 4. DCN sampling + cfs (rounded output); 8 tokens per block
    dcn_sample_kernel<<<NTOK/8, 192>>>(cfs_w, cfs_b, p_dcn);

    // 5. d(+db) = dcn @ out_proj + b   (split-K=2, one launch, 588 CTAs)
    gemm_splitk_kernel<<<dim3(3, MT, 2), thr256>>>(p_dcn, p_w2, out_proj_b, p_zero,
                                                   p_d, p_db, NTOK, Csz, Csz/2, Csz);

    // 6. x2 = x + LN(d + db, rpn1); t = round(LN(x2, norm2))
    ln_fuse2_kernel<<<NTOK, Csz>>>(p_d, p_db, x, rpn1_w, rpn1_b, norm2_w, norm2_b, p_x2, p_t);

    // 7. h1 = round(GELU(t @ fc1 + b))   (N = 768)
    gemm_tf32_kernel<<<dim3(12, MT), thr256>>>(p_t, p_w3, fc1_b, p_h1, NTOK, HID, Csz, 1, 0, 1);

    // 8. h2(+h2b) = h1 @ fc2 + b   (split-K=2, one launch, 588 CTAs)
    gemm_splitk_kernel<<<dim3(3, MT, 2), thr256>>>(p_h1, p_w4, fc2_b, p_zero,
                                                   p_h2, p_h2b, NTOK, Csz, HID/2, HID);

    // 9. out = x2 + LN(h2 + h2b, rpn2)
    ln_kernel<<<NTOK, Csz>>>(p_h2, p_h2b, p_x2, rpn2_w, rpn2_b, outp, 1e-5f, 0);
}

// round 15
// speedup vs baseline: 1.1844x; 1.1844x over previous
#include <cuda_runtime.h>
#include <cuda_bf16.h>
#include <math.h>

// Problem constants (fixed by the reference)
#define BB   4
#define HH   56
#define WW   56
#define Csz  192
#define Gsz  12
#define CG   16
#define Kpts 8
#define HID  768
#define HP   58
#define WP   58
#define NTOK (BB*HH*WW)          // 12544
#define PADSP (HP*WP)            // 3364
#define NOM  288                  // off(192) + mask(96) concatenated

// ---------------- scratch (device globals; no allocation) ----------------
__device__ float g_xln[NTOK*Csz];
__device__ float g_pad[BB*PADSP*Csz];      // padded value (in_proj output)
__device__ float g_x1 [NTOK*Csz];          // dwconv+LN+GELU (tf32-rounded)
__device__ float g_off[NTOK*Csz];          // G*K*2 = 192
__device__ float g_msk[NTOK*Gsz*Kpts];     // 96 logits
__device__ float g_dcn[NTOK*Csz];          // sampling output (tf32-rounded)
__device__ float g_d  [NTOK*Csz];          // out_proj output
__device__ float g_x2 [NTOK*Csz];          // x + LN(d)
__device__ float g_t  [NTOK*Csz];          // LN(x2, norm2) (tf32-rounded)
__device__ float g_h1 [NTOK*HID];          // (tf32-rounded)
__device__ float g_h2 [NTOK*Csz];
// tf32-rounded weight copies
__device__ float g_w1 [Csz*Csz];           // in_proj
__device__ float g_wom[Csz*NOM];           // off | mask concat
__device__ float g_bom[NOM];               // off_b | mask_b concat
__device__ float g_w2 [Csz*Csz];           // out_proj
__device__ float g_w3 [Csz*HID];           // fc1
__device__ float g_w4 [HID*Csz];           // fc2

// ---------------- helpers ----------------
__device__ __forceinline__ float gelu_exact(float x) {
    return 0.5f * x * (1.0f + erff(x * 0.70710678118654752f));
}

__device__ __forceinline__ float round_tf32(float x) {
    unsigned r;
    asm("cvt.rna.tf32.f32 %0, %1;" : "=r"(r) : "f"(x));
    return __uint_as_float(r);
}

__device__ __forceinline__ unsigned smem_u32(const void* p) {
    return (unsigned)__cvta_generic_to_shared(p);
}

__device__ __forceinline__ void cp_async16(unsigned dst, const void* src, int src_bytes) {
    asm volatile("cp.async.cg.shared.global [%0], [%1], 16, %2;"
                 :: "r"(dst), "l"(src), "r"(src_bytes));
}

// ---------------- setup work sizes ----------------
#define W1_SZ (Csz*Csz)
#define WOM_SZ (Csz*NOM)
#define W3_SZ (Csz*HID)
#define PREP_TOTAL (W1_SZ + WOM_SZ + W1_SZ + W3_SZ + W3_SZ + NOM)
#define BORDER_TOTAL (BB*228*Csz)
#define SETUP_TOTAL (PREP_TOTAL + BORDER_TOTAL)
#define SETUP_BLOCKS 513
#define LN_TPB 256
#define LN_TOKPB 8
#define LN_BLOCKS (NTOK/LN_TOKPB)   // 1568

__device__ __forceinline__ void setup_work(int i,
        const float* ipw, const float* offw, const float* maskw,
        const float* opw, const float* f1w, const float* f2w,
        const float* offb, const float* maskb) {
    int j = i;
    if (j < BORDER_TOTAL) {
        const int per_img = 228 * Csz;
        int b = j / per_img;
        int r = j % per_img;
        int cell = r / Csz, c = r % Csz;
        int h, w;
        if      (cell < 58)  { h = 0;              w = cell; }
        else if (cell < 116) { h = HP-1;           w = cell - 58; }
        else if (cell < 172) { h = cell - 116 + 1; w = 0; }
        else                 { h = cell - 172 + 1; w = WP-1; }
        g_pad[((size_t)b*PADSP + (size_t)h*WP + w)*Csz + c] = 0.f;
        return;
    }
    j -= BORDER_TOTAL;
    if (j < W1_SZ) { g_w1[j] = round_tf32(ipw[j]); return; }
    j -= W1_SZ;
    if (j < WOM_SZ) {
        int row = j / NOM, col = j % NOM;
        float v = (col < Csz) ? offw[row*(Gsz*Kpts*2) + col] : maskw[row*(Gsz*Kpts) + col - Csz];
        g_wom[j] = round_tf32(v);
        return;
    }
    j -= WOM_SZ;
    if (j < W1_SZ) { g_w2[j] = round_tf32(opw[j]); return; }
    j -= W1_SZ;
    if (j < W3_SZ) { g_w3[j] = round_tf32(f1w[j]); return; }
    j -= W3_SZ;
    if (j < W3_SZ) { g_w4[j] = round_tf32(f2w[j]); return; }
    j -= W3_SZ;
    g_bom[j] = (j < Csz) ? offb[j] : maskb[j - Csz];
}

// ---------------- warp-per-token LN core ----------------
// Each warp handles one token: lane owns channels [lane*6, lane*6+6) as 3 float2.
struct LnVals { float2 a, b, c; };

__device__ __forceinline__ LnVals ln_load(const float* base) {
    const float2* p = (const float2*)base;
    LnVals v; v.a = p[0]; v.b = p[1]; v.c = p[2]; return v;
}

__device__ __forceinline__ void ln_stats(const LnVals& v, float& mu, float& rs, float eps) {
    float s  = v.a.x + v.a.y + v.b.x + v.b.y + v.c.x + v.c.y;
    float s2 = v.a.x*v.a.x + v.a.y*v.a.y + v.b.x*v.b.x + v.b.y*v.b.y
             + v.c.x*v.c.x + v.c.y*v.c.y;
    #pragma unroll
    for (int o = 16; o; o >>= 1) {
        s  += __shfl_xor_sync(0xffffffffu, s,  o);
        s2 += __shfl_xor_sync(0xffffffffu, s2, o);
    }
    mu = s * (1.0f/Csz);
    float var = s2 * (1.0f/Csz) - mu*mu;
    rs = rsqrtf(var + eps);
}

// ---------------- fat kernel A: LN(x, norm1) -> xln (rounded)  +  setup ----
// blocks [0, LN_BLOCKS): 8 tokens per block (warp each).
// blocks [LN_BLOCKS, LN_BLOCKS+SETUP_BLOCKS): setup.
__global__ __launch_bounds__(LN_TPB) void lnsetup_kernel(
        const float* __restrict__ x,
        const float* __restrict__ w, const float* __restrict__ b,
        const float* __restrict__ ipw,
        const float* __restrict__ offw, const float* __restrict__ maskw,
        const float* __restrict__ opw,
        const float* __restrict__ f1w, const float* __restrict__ f2w,
        const float* __restrict__ offb, const float* __restrict__ maskb) {
    if (blockIdx.x >= LN_BLOCKS) {
        int base = (blockIdx.x - LN_BLOCKS) * LN_TPB + threadIdx.x;
        for (int i = base; i < SETUP_TOTAL; i += SETUP_BLOCKS * LN_TPB)
            setup_work(i, ipw, offw, maskw, opw, f1w, f2w, offb, maskb);
        return;
    }
    int warp = threadIdx.x >> 5, lane = threadIdx.x & 31;
    int n = blockIdx.x * LN_TOKPB + warp;
    int c0 = lane * 6;
    LnVals v = ln_load(x + (size_t)n*Csz + c0);
    float mu, rs;
    ln_stats(v, mu, rs, 1e-5f);
    float2 wa = *(const float2*)(w + c0), wb = *(const float2*)(w + c0 + 2), wc = *(const float2*)(w + c0 + 4);
    float2 ba = *(const float2*)(b + c0), bb = *(const float2*)(b + c0 + 2), bc = *(const float2*)(b + c0 + 4);
    float2* o = (float2*)(g_xln + (size_t)n*Csz + c0);
    float2 r0, r1, r2;
    r0.x = round_tf32((v.a.x - mu)*rs*wa.x + ba.x); r0.y = round_tf32((v.a.y - mu)*rs*wa.y + ba.y);
    r1.x = round_tf32((v.b.x - mu)*rs*wb.x + bb.x); r1.y = round_tf32((v.b.y - mu)*rs*wb.y + bb.y);
    r2.x = round_tf32((v.c.x - mu)*rs*wc.x + bc.x); r2.y = round_tf32((v.c.y - mu)*rs*wc.y + bc.y);
    o[0] = r0; o[1] = r1; o[2] = r2;
}

// ---------------- warp-per-token LN: out = LN(in)*w+b (+ res) ----------------
__global__ __launch_bounds__(LN_TPB) void ln_warp_kernel(
        const float* __restrict__ in, const float* __restrict__ res,
        const float* __restrict__ w, const float* __restrict__ b,
        float* __restrict__ out, float eps) {
    int warp = threadIdx.x >> 5, lane = threadIdx.x & 31;
    int n = blockIdx.x * LN_TOKPB + warp;
    int c0 = lane * 6;
    LnVals v = ln_load(in + (size_t)n*Csz + c0);
    float mu, rs;
    ln_stats(v, mu, rs, eps);
    float2 wa = *(const float2*)(w + c0), wb = *(const float2*)(w + c0 + 2), wc = *(const float2*)(w + c0 + 4);
    float2 ba = *(const float2*)(b + c0), bb = *(const float2*)(b + c0 + 2), bc = *(const float2*)(b + c0 + 4);
    float2 r0, r1, r2;
    r0.x = (v.a.x - mu)*rs*wa.x + ba.x; r0.y = (v.a.y - mu)*rs*wa.y + ba.y;
    r1.x = (v.b.x - mu)*rs*wb.x + bb.x; r1.y = (v.b.y - mu)*rs*wb.y + bb.y;
    r2.x = (v.c.x - mu)*rs*wc.x + bc.x; r2.y = (v.c.y - mu)*rs*wc.y + bc.y;
    if (res) {
        const float2* rp = (const float2*)(res + (size_t)n*Csz + c0);
        float2 q0 = rp[0], q1 = rp[1], q2 = rp[2];
        r0.x += q0.x; r0.y += q0.y;
        r1.x += q1.x; r1.y += q1.y;
        r2.x += q2.x; r2.y += q2.y;
    }
    float2* o = (float2*)(out + (size_t)n*Csz + c0);
    o[0] = r0; o[1] = r1; o[2] = r2;
}

// ---------------- fused warp-per-token: x2 = x + LN(d, rpn1); t = round(LN(x2, norm2)) ----
__global__ __launch_bounds__(LN_TPB) void ln_fuse2_kernel(
        const float* __restrict__ d_in, const float* __restrict__ x_in,
        const float* __restrict__ w1, const float* __restrict__ b1,
        const float* __restrict__ w2, const float* __restrict__ b2,
        float* __restrict__ x2_out, float* __restrict__ t_out) {
    int warp = threadIdx.x >> 5, lane = threadIdx.x & 31;
    int n = blockIdx.x * LN_TOKPB + warp;
    int c0 = lane * 6;
    LnVals v = ln_load(d_in + (size_t)n*Csz + c0);
    float mu, rs;
    ln_stats(v, mu, rs, 1e-5f);
    float2 wa = *(const float2*)(w1 + c0), wb = *(const float2*)(w1 + c0 + 2), wc = *(const float2*)(w1 + c0 + 4);
    float2 ba = *(const float2*)(b1 + c0), bb = *(const float2*)(b1 + c0 + 2), bc = *(const float2*)(b1 + c0 + 4);
    const float2* xp = (const float2*)(x_in + (size_t)n*Csz + c0);
    float2 x0 = xp[0], x1 = xp[1], x2v = xp[2];
    LnVals u;
    u.a.x = x0.x  + (v.a.x - mu)*rs*wa.x + ba.x;
    u.a.y = x0.y  + (v.a.y - mu)*rs*wa.y + ba.y;
    u.b.x = x1.x  + (v.b.x - mu)*rs*wb.x + bb.x;
    u.b.y = x1.y  + (v.b.y - mu)*rs*wb.y + bb.y;
    u.c.x = x2v.x + (v.c.x - mu)*rs*wc.x + bc.x;
    u.c.y = x2v.y + (v.c.y - mu)*rs*wc.y + bc.y;
    float2* xo = (float2*)(x2_out + (size_t)n*Csz + c0);
    xo[0] = u.a; xo[1] = u.b; xo[2] = u.c;

    ln_stats(u, mu, rs, 1e-5f);
    wa = *(const float2*)(w2 + c0); wb = *(const float2*)(w2 + c0 + 2); wc = *(const float2*)(w2 + c0 + 4);
    ba = *(const float2*)(b2 + c0); bb = *(const float2*)(b2 + c0 + 2); bc = *(const float2*)(b2 + c0 + 4);
    float2 r0, r1, r2;
    r0.x = round_tf32((u.a.x - mu)*rs*wa.x + ba.x); r0.y = round_tf32((u.a.y - mu)*rs*wa.y + ba.y);
    r1.x = round_tf32((u.b.x - mu)*rs*wb.x + bb.x); r1.y = round_tf32((u.b.y - mu)*rs*wb.y + bb.y);
    r2.x = round_tf32((u.c.x - mu)*rs*wc.x + bc.x); r2.y = round_tf32((u.c.y - mu)*rs*wc.y + bc.y);
    float2* to = (float2*)(t_out + (size_t)n*Csz + c0);
    to[0] = r0; to[1] = r1; to[2] = r2;
}

// ---------------- GEMM tile body (128x64, 2-stage cp.async, tf32) ----------
#define AS_STRIDE 20
#define BS_STRIDE 72
struct GemmSmem {
    float As[2][128*AS_STRIDE];
    float Bs[2][16*BS_STRIDE];
};

__device__ __forceinline__ void gemm_tile_body(
        GemmSmem* sm, const float* __restrict__ A, const float* __restrict__ W,
        const float* __restrict__ bias, float* __restrict__ C,
        int M, int N, int K, int row0, int col0, int act, int out_mode, int rnd) {
    int tid = threadIdx.x;
    int lane = tid & 31, warp = tid >> 5;
    int gid = lane >> 2, tig = lane & 3;
    int wr = (warp >> 1) * 32;
    int wc = (warp & 1) * 32;

    int a_row = tid >> 1;
    int a_k   = (tid & 1) * 8;
    int b_row = tid >> 4;
    int b_n   = (tid & 15) * 4;

    const float* Abase = A + (size_t)(row0 + a_row)*K + a_k;
    const float* Wbase = W + (size_t)b_row*N + col0 + b_n;
    int b_valid = (col0 + b_n + 4 <= N) ? 16 : 0;

    unsigned as_dst0 = smem_u32(&sm->As[0][a_row*AS_STRIDE + a_k]);
    unsigned as_dst1 = smem_u32(&sm->As[1][a_row*AS_STRIDE + a_k]);
    unsigned bs_dst0 = smem_u32(&sm->Bs[0][b_row*BS_STRIDE + b_n]);
    unsigned bs_dst1 = smem_u32(&sm->Bs[1][b_row*BS_STRIDE + b_n]);

    float acc[2][4][4];
    #pragma unroll
    for (int mi = 0; mi < 2; mi++)
        #pragma unroll
        for (int ni = 0; ni < 4; ni++)
            #pragma unroll
            for (int r = 0; r < 4; r++) acc[mi][ni][r] = 0.f;

    int stages = K / 16;

    cp_async16(as_dst0,      Abase,     16);
    cp_async16(as_dst0 + 16, Abase + 4, 16);
    cp_async16(bs_dst0, Wbase, b_valid);
    asm volatile("cp.async.commit_group;");

    for (int it = 0; it < stages; it++) {
        asm volatile("cp.async.wait_group 0;");
        __syncthreads();

        if (it + 1 < stages) {
            int k0n = (it + 1) * 16;
            const float* An = Abase + k0n;
            const float* Wn = Wbase + (size_t)k0n * N;
            unsigned ad = ((it + 1) & 1) ? as_dst1 : as_dst0;
            unsigned bd = ((it + 1) & 1) ? bs_dst1 : bs_dst0;
            cp_async16(ad,      An,     16);
            cp_async16(ad + 16, An + 4, 16);
            cp_async16(bd, Wn, b_valid);
            asm volatile("cp.async.commit_group;");
        }

        const unsigned* as = (const unsigned*)sm->As[it & 1];
        const unsigned* bs = (const unsigned*)sm->Bs[it & 1];
        #pragma unroll
        for (int ks = 0; ks < 2; ks++) {
            int kb = ks * 8;
            unsigned af[2][4], bf[4][2];
            #pragma unroll
            for (int mi = 0; mi < 2; mi++) {
                int mrow = wr + mi*16 + gid;
                af[mi][0] = as[ mrow   *AS_STRIDE + kb + tig    ];
                af[mi][1] = as[(mrow+8)*AS_STRIDE + kb + tig    ];
                af[mi][2] = as[ mrow   *AS_STRIDE + kb + tig + 4];
                af[mi][3] = as[(mrow+8)*AS_STRIDE + kb + tig + 4];
            }
            #pragma unroll
            for (int ni = 0; ni < 4; ni++) {
                int ncol = wc + ni*8 + gid;
                bf[ni][0] = bs[(kb + tig    )*BS_STRIDE + ncol];
                bf[ni][1] = bs[(kb + tig + 4)*BS_STRIDE + ncol];
            }
            #pragma unroll
            for (int mi = 0; mi < 2; mi++)
                #pragma unroll
                for (int ni = 0; ni < 4; ni++) {
                    asm volatile(
                        "mma.sync.aligned.m16n8k8.row.col.f32.tf32.tf32.f32 "
                        "{%0,%1,%2,%3}, {%4,%5,%6,%7}, {%8,%9}, {%0,%1,%2,%3};"
                        : "+f"(acc[mi][ni][0]), "+f"(acc[mi][ni][1]),
                          "+f"(acc[mi][ni][2]), "+f"(acc[mi][ni][3])
                        : "r"(af[mi][0]), "r"(af[mi][1]), "r"(af[mi][2]), "r"(af[mi][3]),
                          "r"(bf[ni][0]), "r"(bf[ni][1]));
                }
        }
        __syncthreads();
    }

    #pragma unroll
    for (int mi = 0; mi < 2; mi++) {
        #pragma unroll
        for (int ni = 0; ni < 4; ni++) {
            int r0 = row0 + wr + mi*16 + gid;
            int c0 = col0 + wc + ni*8 + 2*tig;
            #pragma unroll
            for (int rr = 0; rr < 2; rr++) {
                int row = r0 + rr*8;
                #pragma unroll
                for (int cc = 0; cc < 2; cc++) {
                    int col = c0 + cc;
                    if (col >= N) continue;
                    float v = acc[mi][ni][rr*2 + cc] + bias[col];
                    if (act == 1) v = gelu_exact(v);
                    if (rnd) v = round_tf32(v);
                    if (out_mode == 1) {
                        int bimg = row / (HH*WW);
                        int hw = row % (HH*WW);
                        int h = hw / WW, w = hw % WW;
                        g_pad[((size_t)bimg*PADSP + (size_t)(h+1)*WP + (w+1))*Csz + col] = v;
                    } else if (out_mode == 2) {
                        if (col < Csz) g_off[(size_t)row*Csz + col] = v;
                        else           g_msk[(size_t)row*(Gsz*Kpts) + col - Csz] = v;
                    } else {
                        C[(size_t)row*N + col] = v;
                    }
                }
            }
        }
    }
}

// ---------------- generic GEMM kernel ----------------
__global__ __launch_bounds__(256) void gemm_tf32_kernel(
        const float* __restrict__ A, const float* __restrict__ W,
        const float* __restrict__ bias, float* __restrict__ C,
        int M, int N, int K, int act, int out_mode, int rnd) {
    __shared__ GemmSmem sm;
    gemm_tile_body(&sm, A, W, bias, C, M, N, K, blockIdx.y*128, blockIdx.x*64,
                   act, out_mode, rnd);
}

// ---------------- fat kernel B: in_proj GEMM + depthwise conv ----------
#define GEMM_BLOCKS (3*(NTOK/128))        // 294
#define DW_BLOCKS   (BB*(HH/4)*WW)        // 3136
__global__ __launch_bounds__(256) void inproj_dw_kernel(
        const float* __restrict__ in_proj_b,
        const float* __restrict__ dww, const float* __restrict__ dwb,
        const float* __restrict__ lnw, const float* __restrict__ lnb) {
    __shared__ GemmSmem sm;   // dw path reuses the first bytes for its reduction
    if (blockIdx.x < GEMM_BLOCKS) {
        int gb = blockIdx.x;
        int col0 = (gb % 3) * 64;
        int row0 = (gb / 3) * 128;
        gemm_tile_body(&sm, g_xln, g_w1, in_proj_b, nullptr, NTOK, Csz, Csz,
                       row0, col0, 0, 1, 0);
        return;
    }
    // ---- dw path: 4 tokens (h0..h0+3, w) ----
    float* redS = (float*)&sm;            // 4*6 sums + 4*6 sqsums = 48 floats
    int blk = blockIdx.x - GEMM_BLOCKS;
    int bimg = blk / ((HH/4)*WW);
    int r = blk % ((HH/4)*WW);
    int h0 = (r / WW) * 4;
    int w = r % WW;
    int c = threadIdx.x;                  // only c < 192 active
    int wid = c >> 5, lane = c & 31;

    float accj[4] = {0.f, 0.f, 0.f, 0.f};
    float s[4], s2[4];
    if (c < Csz) {
        float wt[9];
        #pragma unroll
        for (int i = 0; i < 9; i++) wt[i] = dww[i*Csz + c];
        float vals[6][3];
        #pragma unroll
        for (int rr = 0; rr < 6; rr++) {
            int hh = h0 - 1 + rr;
            #pragma unroll
            for (int cc = 0; cc < 3; cc++) {
                int ww = w - 1 + cc;
                float v = 0.f;
                if (hh >= 0 && hh < HH && ww >= 0 && ww < WW)
                    v = g_xln[((bimg*HH + hh)*WW + ww)*Csz + c];
                vals[rr][cc] = v;
            }
        }
        float bc = dwb[c];
        #pragma unroll
        for (int j = 0; j < 4; j++) {
            float a = 0.f;
            #pragma unroll
            for (int ky = 0; ky < 3; ky++)
                #pragma unroll
                for (int kx = 0; kx < 3; kx++)
                    a += vals[j + ky][kx] * wt[ky*3 + kx];
            accj[j] = a + bc;
        }
        #pragma unroll
        for (int j = 0; j < 4; j++) { s[j] = accj[j]; s2[j] = accj[j]*accj[j]; }
        #pragma unroll
        for (int o = 16; o; o >>= 1) {
            #pragma unroll
            for (int j = 0; j < 4; j++) {
                s[j]  += __shfl_xor_sync(0xffffffffu, s[j],  o);
                s2[j] += __shfl_xor_sync(0xffffffffu, s2[j], o);
            }
        }
        if (lane == 0) {
            #pragma unroll
            for (int j = 0; j < 4; j++) {
                redS[j*6 + wid]      = s[j];
                redS[24 + j*6 + wid] = s2[j];
            }
        }
    }
    __syncthreads();
    if (c < Csz) {
        float lw = lnw[c], lb = lnb[c];
        #pragma unroll
        for (int j = 0; j < 4; j++) {
            float S = 0.f, S2 = 0.f;
            #pragma unroll
            for (int i = 0; i < 6; i++) { S += redS[j*6 + i]; S2 += redS[24 + j*6 + i]; }
            float mu  = S * (1.0f/Csz);
            float var = S2 * (1.0f/Csz) - mu*mu;
            float y = (accj[j] - mu) * rsqrtf(var + 1e-6f) * lw + lb;
            int n = (bimg*HH + h0 + j)*WW + w;
            g_x1[n*Csz + c] = round_tf32(gelu_exact(y));
        }
    }
}

// ---------------- DCNv3 sampling: 4 channels/thread, 4 tokens/block ----------
// (round-11 proven config: 48 threads/token, float4 gathers, predicated loads)
__global__ void dcn_sample_kernel(const float* __restrict__ cfs_w, const float* __restrict__ cfs_b,
                                  float* __restrict__ out) {
    int t = threadIdx.x;
    int tok = t / 48;
    int tt = t % 48;
    int n = blockIdx.x * 4 + tok;
    int g = tt >> 2, l = tt & 3;
    int bimg = n / (HH*WW);
    int hw = n % (HH*WW);
    int h = hw / WW, w = hw % WW;

    __shared__ float4 x1s[4][48];
    x1s[tok][tt] = *(const float4*)&g_x1[n*Csz + tt*4];
    __syncthreads();

    const float4* cwv = (const float4*)(cfs_w + g*Csz);
    float p = 0.f;
    #pragma unroll
    for (int c = l; c < Csz/4; c += 4) {
        float4 a = x1s[tok][c], b = cwv[c];
        p += a.x*b.x + a.y*b.y + a.z*b.z + a.w*b.w;
    }
    p += __shfl_xor_sync(0xffffffffu, p, 1, 4);
    p += __shfl_xor_sync(0xffffffffu, p, 2, 4);
    float cfsv = 1.0f / (1.0f + expf(-(p + cfs_b[g])));

    float m[Kpts];
    float mx = -1e30f;
    #pragma unroll
    for (int k = 0; k < Kpts; k++) {
        m[k] = g_msk[n*(Gsz*Kpts) + g*Kpts + k];
        mx = fmaxf(mx, m[k]);
    }
    float msum = 0.f;
    #pragma unroll
    for (int k = 0; k < Kpts; k++) { m[k] = expf(m[k] - mx); msum += m[k]; }
    float minv = 1.0f / msum;

    const float gx[Kpts] = {-1,-1,-1, 0, 0, 1, 1, 1};
    const float gy[Kpts] = {-1, 0, 1,-1, 1,-1, 0, 1};
    const float* vb = g_pad + (size_t)bimg*PADSP*Csz;
    int ch = g*CG + 4*l;

    float ax = 0.f, ay = 0.f, az = 0.f, aw = 0.f;
    #pragma unroll
    for (int k = 0; k < Kpts; k++) {
        float ox = g_off[n*Csz + (g*Kpts + k)*2 + 0];
        float oy = g_off[n*Csz + (g*Kpts + k)*2 + 1];
        float px = (float)(w + 1) + gx[k] + ox;
        float py = (float)(h + 1) + gy[k] + oy;
        float x0 = floorf(px), y0 = floorf(py);
        float wx = px - x0, wy = py - y0;
        int ix0 = (int)x0, iy0 = (int)y0;

        float4 s00 = {0,0,0,0}, s01 = {0,0,0,0}, s10 = {0,0,0,0}, s11 = {0,0,0,0};
        if (iy0   >= 0 && iy0   < HP && ix0   >= 0 && ix0   < WP) s00 = *(const float4*)&vb[((size_t)iy0*WP + ix0)*Csz + ch];
        if (iy0   >= 0 && iy0   < HP && ix0+1 >= 0 && ix0+1 < WP) s01 = *(const float4*)&vb[((size_t)iy0*WP + ix0+1)*Csz + ch];
        if (iy0+1 >= 0 && iy0+1 < HP && ix0   >= 0 && ix0   < WP) s10 = *(const float4*)&vb[((size_t)(iy0+1)*WP + ix0)*Csz + ch];
        if (iy0+1 >= 0 && iy0+1 < HP && ix0+1 >= 0 && ix0+1 < WP) s11 = *(const float4*)&vb[((size_t)(iy0+1)*WP + ix0+1)*Csz + ch];

        float w00 = (1.f-wy)*(1.f-wx), w01 = (1.f-wy)*wx;
        float w10 = wy*(1.f-wx),       w11 = wy*wx;
        float mk = m[k]*minv;
        ax += mk * (s00.x*w00 + s01.x*w01 + s10.x*w10 + s11.x*w11);
        ay += mk * (s00.y*w00 + s01.y*w01 + s10.y*w10 + s11.y*w11);
        az += mk * (s00.z*w00 + s01.z*w01 + s10.z*w10 + s11.z*w11);
        aw += mk * (s00.w*w00 + s01.w*w01 + s10.w*w10 + s11.w*w11);
    }

    float4 xpv = *(const float4*)&vb[((size_t)(h+1)*WP + (w+1))*Csz + ch];
    float4 o;
    o.x = round_tf32(ax*(1.0f - cfsv) + xpv.x*cfsv);
    o.y = round_tf32(ay*(1.0f - cfsv) + xpv.y*cfsv);
    o.z = round_tf32(az*(1.0f - cfsv) + xpv.z*cfsv);
    o.w = round_tf32(aw*(1.0f - cfsv) + xpv.w*cfsv);
    *(float4*)&out[n*Csz + ch] = o;
}

// ---------------- launch ----------------
extern "C" void kernel_launch(void* const* d_in, const int* in_sizes, int n_in,
                              void* d_out, int out_size) {
    const float* x        = (const float*)d_in[0];
    const float* norm1_w  = (const float*)d_in[1];
    const float* norm1_b  = (const float*)d_in[2];
    const float* norm2_w  = (const float*)d_in[3];
    const float* norm2_b  = (const float*)d_in[4];
    const float* rpn1_w   = (const float*)d_in[5];
    const float* rpn1_b   = (const float*)d_in[6];
    const float* rpn2_w   = (const float*)d_in[7];
    const float* rpn2_b   = (const float*)d_in[8];
    const float* in_proj_w= (const float*)d_in[9];
    const float* in_proj_b= (const float*)d_in[10];
    const float* dw_w     = (const float*)d_in[11];
    const float* dw_b     = (const float*)d_in[12];
    const float* dw_ln_w  = (const float*)d_in[13];
    const float* dw_ln_b  = (const float*)d_in[14];
    const float* off_w    = (const float*)d_in[15];
    const float* off_b    = (const float*)d_in[16];
    const float* mask_w   = (const float*)d_in[17];
    const float* mask_b   = (const float*)d_in[18];
    const float* cfs_w    = (const float*)d_in[19];
    const float* cfs_b    = (const float*)d_in[20];
    const float* out_proj_w = (const float*)d_in[21];
    const float* out_proj_b = (const float*)d_in[22];
    const float* fc1_w    = (const float*)d_in[23];
    const float* fc1_b    = (const float*)d_in[24];
    const float* fc2_w    = (const float*)d_in[25];
    const float* fc2_b    = (const float*)d_in[26];
    float* outp = (float*)d_out;

    float *p_dcn, *p_d, *p_x2, *p_t, *p_h1, *p_h2;
    float *p_x1, *p_wom, *p_bom, *p_w2, *p_w3, *p_w4;
    cudaGetSymbolAddress((void**)&p_x1,  g_x1);
    cudaGetSymbolAddress((void**)&p_dcn, g_dcn);
    cudaGetSymbolAddress((void**)&p_d,   g_d);
    cudaGetSymbolAddress((void**)&p_x2,  g_x2);
    cudaGetSymbolAddress((void**)&p_t,   g_t);
    cudaGetSymbolAddress((void**)&p_h1,  g_h1);
    cudaGetSymbolAddress((void**)&p_h2,  g_h2);
    cudaGetSymbolAddress((void**)&p_wom, g_wom);
    cudaGetSymbolAddress((void**)&p_bom, g_bom);
    cudaGetSymbolAddress((void**)&p_w2,  g_w2);
    cudaGetSymbolAddress((void**)&p_w3,  g_w3);
    cudaGetSymbolAddress((void**)&p_w4,  g_w4);

    dim3 thr256(256);
    const int MT = NTOK/128;   // 98 M-tiles

    // 1. LN(x, norm1) warp-per-token + setup — one fat launch
    lnsetup_kernel<<<LN_BLOCKS + SETUP_BLOCKS, LN_TPB>>>(x, norm1_w, norm1_b,
        in_proj_w, off_w, mask_w, out_proj_w, fc1_w, fc2_w, off_b, mask_b);

    // 2. in_proj GEMM (-> padded value buffer)  +  dwconv/LN/GELU — one fat launch
    inproj_dw_kernel<<<GEMM_BLOCKS + DW_BLOCKS, thr256>>>(in_proj_b, dw_w, dw_b,
        dw_ln_w, dw_ln_b);

    // 3. off|mask = x1 @ [off_w|mask_w] + bias   (merged, N=288)
    gemm_tf32_kernel<<<dim3(5, MT), thr256>>>(p_x1, p_wom, p_bom, nullptr, NTOK, NOM, Csz, 0, 2, 0);

    // 4. DCN sampling + cfs (rounded output); 4 tokens per block
    dcn_sample_kernel<<<NTOK/4, Csz>>>(cfs_w, cfs_b, p_dcn);

    // 5. d = dcn @ out_proj + b
    gemm_tf32_kernel<<<dim3(3, MT), thr256>>>(p_dcn, p_w2, out_proj_b, p_d, NTOK, Csz, Csz, 0, 0, 0);

    // 6. x2 = x + LN(d, rpn1); t = round(LN(x2, norm2)) — warp-per-token
    ln_fuse2_kernel<<<LN_BLOCKS, LN_TPB>>>(p_d, x, rpn1_w, rpn1_b, norm2_w, norm2_b, p_x2, p_t);

    // 7. h1 = round(GELU(t @ fc1 + b))   (N = 768)
    gemm_tf32_kernel<<<dim3(12, MT), thr256>>>(p_t, p_w3, fc1_b, p_h1, NTOK, HID, Csz, 1, 0, 1);

    // 8. h2 = h1 @ fc2 + b   (K = 768)
    gemm_tf32_kernel<<<dim3(3, MT), thr256>>>(p_h1, p_w4, fc2_b, p_h2, NTOK, Csz, HID, 0, 0, 0);

    // 9. out = x2 + LN(h2, rpn2) — warp-per-token
    ln_warp_kernel<<<LN_BLOCKS, LN_TPB>>>(p_h2, p_x2, rpn2_w, rpn2_b, outp, 1e-5f);
}